// round 1
// baseline (speedup 1.0000x reference)
#include <cuda_runtime.h>
#include <cstdint>

// Problem dims (fixed by the dataset):
//   x: [32,196,768] -> X[M=6272, K=768]
//   weight_components: [4, 768, 192]  (n, out_blk, in_blk)
//   bias: [3072]
//   out: [6272, 3072]
// out[b, ki*768+o] = sum_j sum_c x[b, j*192+c] * W[(ki-j)%4, o, c] + bias
// == X @ WT  with  WT[j*192+c][ki*768+o] = W[(ki-j)%4, o, c]

#define M_DIM 6272
#define K_DIM 768
#define N_DIM 3072

// Scratch (allocation-free rule: __device__ globals)
__device__ float g_Xc[M_DIM * K_DIM];   // tf32-rounded X
__device__ float g_WT[K_DIM * N_DIM];   // tf32-rounded circulant weight, [K][N]

__device__ __forceinline__ float f2tf32(float x) {
    uint32_t u;
    asm("cvt.rna.tf32.f32 %0, %1;" : "=r"(u) : "f"(x));
    return __uint_as_float(u);
}

// ---------------------------------------------------------------------------
// Prep 1: round X to tf32 (vectorized)
// ---------------------------------------------------------------------------
__global__ void prep_x_kernel(const float4* __restrict__ x) {
    int i = blockIdx.x * blockDim.x + threadIdx.x;   // grid covers exactly M*K/4
    float4 v = x[i];
    v.x = f2tf32(v.x);
    v.y = f2tf32(v.y);
    v.z = f2tf32(v.z);
    v.w = f2tf32(v.w);
    reinterpret_cast<float4*>(g_Xc)[i] = v;
}

// ---------------------------------------------------------------------------
// Prep 2: materialize circulant weight transposed, tf32-rounded
// ---------------------------------------------------------------------------
__global__ void prep_w_kernel(const float* __restrict__ w) {
    int idx = blockIdx.x * blockDim.x + threadIdx.x;  // grid covers exactly K*N
    int k = idx / N_DIM;          // 0..767
    int n = idx - k * N_DIM;      // 0..3071
    int j  = k / 192;
    int c  = k - j * 192;
    int ki = n / 768;
    int o  = n - ki * 768;
    int comp = (ki - j + 4) & 3;
    g_WT[idx] = f2tf32(w[(comp * 768 + o) * 192 + c]);
}

// ---------------------------------------------------------------------------
// GEMM: C = X @ WT + bias   using mma.sync m16n8k8 tf32
// CTA tile 128x128x32, 256 threads (8 warps as 2x4), warp tile 64x32.
// ---------------------------------------------------------------------------
#define BM 128
#define BN 128
#define BK 32
#define A_LD 36    // As[row][col], (4m+k) distinct mod 32 -> conflict-free frag reads
#define B_LD 136   // Bs[row][col], (8k+n) distinct mod 32 -> conflict-free frag reads

__device__ __forceinline__ void mma_tf32(float* c, const uint32_t* a, const uint32_t* b) {
    asm volatile(
        "mma.sync.aligned.m16n8k8.row.col.f32.tf32.tf32.f32 "
        "{%0,%1,%2,%3}, {%4,%5,%6,%7}, {%8,%9}, {%0,%1,%2,%3};"
        : "+f"(c[0]), "+f"(c[1]), "+f"(c[2]), "+f"(c[3])
        : "r"(a[0]), "r"(a[1]), "r"(a[2]), "r"(a[3]),
          "r"(b[0]), "r"(b[1]));
}

__global__ __launch_bounds__(256, 2)
void gemm_tf32_kernel(const float* __restrict__ bias, float* __restrict__ out) {
    __shared__ float As[BM * A_LD];
    __shared__ float Bs[BK * B_LD];

    const int tid  = threadIdx.x;
    const int bm   = blockIdx.y * BM;
    const int bn   = blockIdx.x * BN;
    const int warp = tid >> 5;
    const int lane = tid & 31;
    const int g    = lane >> 2;   // group id 0..7
    const int tig  = lane & 3;    // thread in group 0..3

    const int wm = (warp & 1) * 64;   // warp m offset in CTA tile
    const int wn = (warp >> 1) * 32;  // warp n offset in CTA tile

    float acc[4][4][4];
#pragma unroll
    for (int mi = 0; mi < 4; mi++)
#pragma unroll
        for (int ni = 0; ni < 4; ni++)
#pragma unroll
            for (int r = 0; r < 4; r++) acc[mi][ni][r] = 0.0f;

    // global->smem load indices
    const int arow = tid >> 3;           // 0..31 (step 32 over 128 rows)
    const int acol = (tid & 7) << 2;     // 0,4,...,28
    const int brow = tid >> 5;           // 0..7  (step 8 over 32 rows)
    const int bcol = (tid & 31) << 2;    // 0,4,...,124

    for (int kt = 0; kt < K_DIM; kt += BK) {
        __syncthreads();   // protect smem reuse from previous iteration's reads
#pragma unroll
        for (int i = 0; i < 4; i++) {
            int r = arow + i * 32;
            float4 v = *reinterpret_cast<const float4*>(
                &g_Xc[(bm + r) * K_DIM + kt + acol]);
            *reinterpret_cast<float4*>(&As[r * A_LD + acol]) = v;
        }
#pragma unroll
        for (int i = 0; i < 4; i++) {
            int r = brow + i * 8;
            float4 v = *reinterpret_cast<const float4*>(
                &g_WT[(kt + r) * N_DIM + bn + bcol]);
            *reinterpret_cast<float4*>(&Bs[r * B_LD + bcol]) = v;
        }
        __syncthreads();

#pragma unroll
        for (int ks = 0; ks < BK; ks += 8) {
            uint32_t a[4][4], b[4][2];
#pragma unroll
            for (int mi = 0; mi < 4; mi++) {
                int row = wm + mi * 16 + g;
                a[mi][0] = __float_as_uint(As[row * A_LD + ks + tig]);
                a[mi][1] = __float_as_uint(As[(row + 8) * A_LD + ks + tig]);
                a[mi][2] = __float_as_uint(As[row * A_LD + ks + tig + 4]);
                a[mi][3] = __float_as_uint(As[(row + 8) * A_LD + ks + tig + 4]);
            }
#pragma unroll
            for (int ni = 0; ni < 4; ni++) {
                int col = wn + ni * 8 + g;
                b[ni][0] = __float_as_uint(Bs[(ks + tig) * B_LD + col]);
                b[ni][1] = __float_as_uint(Bs[(ks + tig + 4) * B_LD + col]);
            }
#pragma unroll
            for (int mi = 0; mi < 4; mi++)
#pragma unroll
                for (int ni = 0; ni < 4; ni++)
                    mma_tf32(acc[mi][ni], a[mi], b[ni]);
        }
    }

    // Epilogue: += bias, vectorized float2 stores
#pragma unroll
    for (int mi = 0; mi < 4; mi++) {
        int row0 = bm + wm + mi * 16 + g;
#pragma unroll
        for (int ni = 0; ni < 4; ni++) {
            int col = bn + wn + ni * 8 + 2 * tig;
            float b0 = bias[col];
            float b1 = bias[col + 1];
            float2 v0 = make_float2(acc[mi][ni][0] + b0, acc[mi][ni][1] + b1);
            float2 v1 = make_float2(acc[mi][ni][2] + b0, acc[mi][ni][3] + b1);
            *reinterpret_cast<float2*>(&out[(size_t)row0 * N_DIM + col]) = v0;
            *reinterpret_cast<float2*>(&out[(size_t)(row0 + 8) * N_DIM + col]) = v1;
        }
    }
}

// ---------------------------------------------------------------------------
extern "C" void kernel_launch(void* const* d_in, const int* in_sizes, int n_in,
                              void* d_out, int out_size) {
    const float* x    = (const float*)d_in[0];   // [32,196,768]
    const float* w    = (const float*)d_in[1];   // [4,768,192]
    const float* bias = (const float*)d_in[2];   // [3072]
    float* out = (float*)d_out;                  // [32,196,3072]

    // Prep: tf32-round X (M*K/4 float4 elems = 1,204,224 -> 4704 blocks x 256)
    prep_x_kernel<<<(M_DIM * K_DIM / 4) / 256, 256>>>(
        reinterpret_cast<const float4*>(x));
    // Prep: build circulant WT (K*N = 2,359,296 -> 9216 blocks x 256)
    prep_w_kernel<<<(K_DIM * N_DIM) / 256, 256>>>(w);

    dim3 grid(N_DIM / BN, M_DIM / BM);  // 24 x 49
    gemm_tf32_kernel<<<grid, 256>>>(bias, out);
}

// round 2
// speedup vs baseline: 1.8384x; 1.8384x over previous
#include <cuda_runtime.h>
#include <cstdint>

// HypercomplexLinear via DFT-4 diagonalization of the block-circulant weight.
//   x: [32,196,768] -> X[M=6272][j=4][c=192]
//   out_k = sum_j x_j @ W_{(k-j)%4}^T  (circular convolution over Z4)
// DFT4 (twiddles +-1, +-i):
//   X0=x0+x1+x2+x3, X2=x0-x1+x2-x3, X1=(x0-x2)-i(x1-x3)=Xr-i*Xs  (W likewise)
//   Out0=X0 W0^T, Out2=X2 W2^T, Out1=X1 W1^T = P - iQ
//     P = Xr Wr^T - Xs Ws^T,  Q = Xr Ws^T + Xs Wr^T
//   out_0=(Out0+Out2+2P)/4, out_1=(Out0-Out2+2Q)/4,
//   out_2=(Out0+Out2-2P)/4, out_3=(Out0-Out2-2Q)/4
// => 6 GEMM-blocks instead of 16 (FLOPs 29.6G -> 11.1G).

#define M_DIM 6272
#define KX    768     // width of transformed X  [X0|X2|Xr|Xs]
#define NG    3072    // width of G = [Out0|Out2|P|Q]

__device__ float g_Xt[M_DIM * KX];     // transformed X, tf32-rounded
__device__ float g_W0[192 * 768];      // W0^T  [c][o]
__device__ float g_W2[192 * 768];      // W2^T
__device__ float g_WC[384 * 1536];     // [[Wr|Ws],[-Ws|Wr]]  [k][n]
__device__ float g_G [M_DIM * NG];     // intermediate

__device__ __forceinline__ float f2tf32(float x) {
    uint32_t u; asm("cvt.rna.tf32.f32 %0, %1;" : "=r"(u) : "f"(x));
    return __uint_as_float(u);
}
__device__ __forceinline__ float4 tf4(float4 v) {
    v.x = f2tf32(v.x); v.y = f2tf32(v.y); v.z = f2tf32(v.z); v.w = f2tf32(v.w);
    return v;
}
__device__ __forceinline__ float4 add4(float4 a, float4 b) {
    return make_float4(a.x+b.x, a.y+b.y, a.z+b.z, a.w+b.w);
}
__device__ __forceinline__ float4 sub4(float4 a, float4 b) {
    return make_float4(a.x-b.x, a.y-b.y, a.z-b.z, a.w-b.w);
}

// ---------------------------------------------------------------------------
// Prep 1: X transform.  One thread per (b, c4): reads x[b][j][c4..+3] j=0..3.
// ---------------------------------------------------------------------------
__global__ void prep_xt_kernel(const float* __restrict__ x) {
    int idx = blockIdx.x * blockDim.x + threadIdx.x;   // 6272*48
    int b  = idx / 48;
    int c4 = (idx - b * 48) * 4;
    const float* xb = x + (size_t)b * KX;
    float4 v0 = *reinterpret_cast<const float4*>(xb + 0   + c4);
    float4 v1 = *reinterpret_cast<const float4*>(xb + 192 + c4);
    float4 v2 = *reinterpret_cast<const float4*>(xb + 384 + c4);
    float4 v3 = *reinterpret_cast<const float4*>(xb + 576 + c4);
    float4 e = add4(v0, v2), o = add4(v1, v3);
    float4 r = sub4(v0, v2), s = sub4(v1, v3);
    float* yb = g_Xt + (size_t)b * KX;
    *reinterpret_cast<float4*>(yb + 0   + c4) = tf4(add4(e, o));  // X0
    *reinterpret_cast<float4*>(yb + 192 + c4) = tf4(sub4(e, o));  // X2
    *reinterpret_cast<float4*>(yb + 384 + c4) = tf4(r);           // Xr
    *reinterpret_cast<float4*>(yb + 576 + c4) = tf4(s);           // Xs
}

// ---------------------------------------------------------------------------
// Prep 2: W transform. idx = o*192 + c (coalesced reads of w[m][o][c]).
// ---------------------------------------------------------------------------
__global__ void prep_wt_kernel(const float* __restrict__ w) {
    int idx = blockIdx.x * blockDim.x + threadIdx.x;   // 147456
    int o = idx / 192;
    int c = idx - o * 192;
    float w0 = w[idx];
    float w1 = w[147456 + idx];
    float w2 = w[294912 + idx];
    float w3 = w[442368 + idx];
    g_W0[c * 768 + o] = f2tf32(w0 + w1 + w2 + w3);
    g_W2[c * 768 + o] = f2tf32(w0 - w1 + w2 - w3);
    float wr = f2tf32(w0 - w2);
    float ws = f2tf32(w1 - w3);
    g_WC[c * 1536 + o]                 = wr;   // P += Xr*Wr
    g_WC[c * 1536 + 768 + o]           = ws;   // Q += Xr*Ws
    g_WC[(192 + c) * 1536 + o]         = -ws;  // P -= Xs*Ws
    g_WC[(192 + c) * 1536 + 768 + o]   = wr;   // Q += Xs*Wr
}

// ---------------------------------------------------------------------------
// Pipelined tf32 GEMM: G = [Xseg] @ Bseg, 3-stage cp.async, 128x128x32 tile.
// ---------------------------------------------------------------------------
#define BM 128
#define BN 128
#define BK 32
#define A_LD 36
#define B_LD 136
#define ASZ (BM * A_LD)     // 4608 floats
#define BSZ (BK * B_LD)     // 4352 floats
#define STG_F (ASZ + BSZ)   // floats per stage
#define STAGES 3
#define SMEM_BYTES (STAGES * STG_F * 4)

__device__ __forceinline__ void mma_tf32(float* c, const uint32_t* a, const uint32_t* b) {
    asm volatile(
        "mma.sync.aligned.m16n8k8.row.col.f32.tf32.tf32.f32 "
        "{%0,%1,%2,%3}, {%4,%5,%6,%7}, {%8,%9}, {%0,%1,%2,%3};"
        : "+f"(c[0]), "+f"(c[1]), "+f"(c[2]), "+f"(c[3])
        : "r"(a[0]), "r"(a[1]), "r"(a[2]), "r"(a[3]),
          "r"(b[0]), "r"(b[1]));
}

__global__ __launch_bounds__(256)
void gemm_pipelined_kernel() {
    extern __shared__ float sm[];
    const int nt = blockIdx.x;           // 0..23
    const int bm = blockIdx.y * BM;
    const int bn = nt * BN;              // column in G

    int aoff, Kseg, ldB, bnl;
    const float* Bg;
    if (nt < 6)       { aoff = 0;   Kseg = 192; ldB = 768;  bnl = nt * 128;        Bg = g_W0; }
    else if (nt < 12) { aoff = 192; Kseg = 192; ldB = 768;  bnl = (nt - 6) * 128;  Bg = g_W2; }
    else              { aoff = 384; Kseg = 384; ldB = 1536; bnl = (nt - 12) * 128; Bg = g_WC; }
    const int KT = Kseg / BK;

    const int tid  = threadIdx.x;
    const int warp = tid >> 5;
    const int lane = tid & 31;
    const int g    = lane >> 2;
    const int tig  = lane & 3;
    const int wm   = (warp & 1) * 64;
    const int wn   = (warp >> 1) * 32;

    const int arow = tid >> 3;           // 0..31
    const int acol = (tid & 7) << 2;     // 0..28
    const int brow = tid >> 5;           // 0..7
    const int bcol = (tid & 31) << 2;    // 0..124

    const float* gA = g_Xt + (size_t)bm * KX + aoff;
    uint32_t smem_base = (uint32_t)__cvta_generic_to_shared(sm);

    auto load_stage = [&](int s, int kt0) {
        uint32_t abase = smem_base + (uint32_t)(s * STG_F) * 4u;
#pragma unroll
        for (int i = 0; i < 4; i++) {
            int r = arow + i * 32;
            uint32_t d = abase + (uint32_t)(r * A_LD + acol) * 4u;
            const float* p = gA + (size_t)r * KX + kt0 * BK + acol;
            asm volatile("cp.async.cg.shared.global [%0], [%1], 16;\n" :: "r"(d), "l"(p));
        }
        uint32_t bbase = abase + (uint32_t)ASZ * 4u;
#pragma unroll
        for (int i = 0; i < 4; i++) {
            int r = brow + i * 8;
            uint32_t d = bbase + (uint32_t)(r * B_LD + bcol) * 4u;
            const float* p = Bg + (size_t)(kt0 * BK + r) * ldB + bnl + bcol;
            asm volatile("cp.async.cg.shared.global [%0], [%1], 16;\n" :: "r"(d), "l"(p));
        }
    };

    float acc[4][4][4];
#pragma unroll
    for (int mi = 0; mi < 4; mi++)
#pragma unroll
        for (int ni = 0; ni < 4; ni++)
#pragma unroll
            for (int r = 0; r < 4; r++) acc[mi][ni][r] = 0.0f;

    int fetch = 0;
#pragma unroll
    for (int s = 0; s < STAGES - 1; s++) {
        if (fetch < KT) load_stage(s, fetch);
        asm volatile("cp.async.commit_group;\n");
        fetch++;
    }
    asm volatile("cp.async.wait_group %0;\n" :: "n"(STAGES - 2));
    __syncthreads();

    for (int kt = 0; kt < KT; kt++) {
        if (fetch < KT) load_stage(fetch % STAGES, fetch);
        asm volatile("cp.async.commit_group;\n");
        fetch++;

        const float* As = sm + (kt % STAGES) * STG_F;
        const float* Bs = As + ASZ;

#pragma unroll
        for (int ks = 0; ks < BK; ks += 8) {
            uint32_t a[4][4], b[4][2];
#pragma unroll
            for (int mi = 0; mi < 4; mi++) {
                int row = wm + mi * 16 + g;
                a[mi][0] = __float_as_uint(As[row * A_LD + ks + tig]);
                a[mi][1] = __float_as_uint(As[(row + 8) * A_LD + ks + tig]);
                a[mi][2] = __float_as_uint(As[row * A_LD + ks + tig + 4]);
                a[mi][3] = __float_as_uint(As[(row + 8) * A_LD + ks + tig + 4]);
            }
#pragma unroll
            for (int ni = 0; ni < 4; ni++) {
                int col = wn + ni * 8 + g;
                b[ni][0] = __float_as_uint(Bs[(ks + tig) * B_LD + col]);
                b[ni][1] = __float_as_uint(Bs[(ks + tig + 4) * B_LD + col]);
            }
#pragma unroll
            for (int mi = 0; mi < 4; mi++)
#pragma unroll
                for (int ni = 0; ni < 4; ni++)
                    mma_tf32(acc[mi][ni], a[mi], b[ni]);
        }

        asm volatile("cp.async.wait_group %0;\n" :: "n"(STAGES - 2));
        __syncthreads();
    }

    // Epilogue: raw G (no bias here)
#pragma unroll
    for (int mi = 0; mi < 4; mi++) {
        int row0 = bm + wm + mi * 16 + g;
#pragma unroll
        for (int ni = 0; ni < 4; ni++) {
            int col = bn + wn + ni * 8 + 2 * tig;
            float2 v0 = make_float2(acc[mi][ni][0], acc[mi][ni][1]);
            float2 v1 = make_float2(acc[mi][ni][2], acc[mi][ni][3]);
            *reinterpret_cast<float2*>(&g_G[(size_t)row0 * NG + col]) = v0;
            *reinterpret_cast<float2*>(&g_G[(size_t)(row0 + 8) * NG + col]) = v1;
        }
    }
}

// ---------------------------------------------------------------------------
// Combine: out_k from Out0/Out2/P/Q + bias. One thread per (b, o4).
// ---------------------------------------------------------------------------
__global__ void combine_kernel(const float* __restrict__ bias,
                               float* __restrict__ out) {
    int idx = blockIdx.x * blockDim.x + threadIdx.x;   // 6272*192
    int b  = idx / 192;
    int o4 = idx - b * 192;
    const float4* Gr = reinterpret_cast<const float4*>(g_G + (size_t)b * NG);
    float4 a0 = Gr[o4];
    float4 a2 = Gr[192 + o4];
    float4 p  = Gr[384 + o4];
    float4 q  = Gr[576 + o4];
    const float4* bs = reinterpret_cast<const float4*>(bias);
    float4 b0 = bs[o4], b1 = bs[192 + o4], b2 = bs[384 + o4], b3 = bs[576 + o4];

    float4 s = make_float4(0.25f*(a0.x+a2.x), 0.25f*(a0.y+a2.y),
                           0.25f*(a0.z+a2.z), 0.25f*(a0.w+a2.w));
    float4 d = make_float4(0.25f*(a0.x-a2.x), 0.25f*(a0.y-a2.y),
                           0.25f*(a0.z-a2.z), 0.25f*(a0.w-a2.w));
    float4 ph = make_float4(0.5f*p.x, 0.5f*p.y, 0.5f*p.z, 0.5f*p.w);
    float4 qh = make_float4(0.5f*q.x, 0.5f*q.y, 0.5f*q.z, 0.5f*q.w);

    float4* ob = reinterpret_cast<float4*>(out + (size_t)b * NG);
    ob[o4]       = make_float4(s.x+ph.x+b0.x, s.y+ph.y+b0.y, s.z+ph.z+b0.z, s.w+ph.w+b0.w);
    ob[192 + o4] = make_float4(d.x+qh.x+b1.x, d.y+qh.y+b1.y, d.z+qh.z+b1.z, d.w+qh.w+b1.w);
    ob[384 + o4] = make_float4(s.x-ph.x+b2.x, s.y-ph.y+b2.y, s.z-ph.z+b2.z, s.w-ph.w+b2.w);
    ob[576 + o4] = make_float4(d.x-qh.x+b3.x, d.y-qh.y+b3.y, d.z-qh.z+b3.z, d.w-qh.w+b3.w);
}

// ---------------------------------------------------------------------------
extern "C" void kernel_launch(void* const* d_in, const int* in_sizes, int n_in,
                              void* d_out, int out_size) {
    const float* x    = (const float*)d_in[0];   // [32,196,768]
    const float* w    = (const float*)d_in[1];   // [4,768,192]
    const float* bias = (const float*)d_in[2];   // [3072]
    float* out = (float*)d_out;                  // [32,196,3072]

    cudaFuncSetAttribute(gemm_pipelined_kernel,
                         cudaFuncAttributeMaxDynamicSharedMemorySize, SMEM_BYTES);

    prep_xt_kernel<<<(M_DIM * 48) / 256, 256>>>(x);        // 1176 blocks
    prep_wt_kernel<<<147456 / 256, 256>>>(w);              // 576 blocks

    dim3 grid(NG / BN, M_DIM / BM);                        // 24 x 49
    gemm_pipelined_kernel<<<grid, 256, SMEM_BYTES>>>();

    combine_kernel<<<(M_DIM * 192) / 256, 256>>>(bias, out);  // 4704 blocks
}